// round 13
// baseline (speedup 1.0000x reference)
#include <cuda_runtime.h>
#include <math_constants.h>

#define IW 224
#define IH 224
#define CCH 32
#define RB 32          // output rows per block
#define TROWS 36       // RB + 4 halo
#define TSTRIDE 232    // 228 cols (224 + 4 halo) padded

typedef unsigned long long u64;

// packed fp32 add (Blackwell f32x2 pipe; only reachable via PTX)
__device__ __forceinline__ u64 fadd2(u64 a, u64 b) {
    u64 r; asm("add.rn.f32x2 %0, %1, %2;" : "=l"(r) : "l"(a), "l"(b)); return r;
}
__device__ __forceinline__ u64 pk(float lo, float hi) {
    u64 r; asm("mov.b64 %0, {%1, %2};" : "=l"(r) : "f"(lo), "f"(hi)); return r;
}
__device__ __forceinline__ void upk(float& lo, float& hi, u64 v) {
    asm("mov.b64 {%0, %1}, %2;" : "=f"(lo), "=f"(hi) : "l"(v));
}

// out[b,c,y,x] = max_{i,j} x[b,c,y+i-2,x+j-2] + kernel[c,0,4-i,4-j], oob -> -inf
// tile[r][c]: global row y0-2+r, global col c-2. Cols 0,1,226,227 always -inf.
__global__ void __launch_bounds__(224, 5)
tropical_conv2d_kernel(const float* __restrict__ x,
                       const float* __restrict__ kw,
                       float* __restrict__ out) {
    __shared__ float tile[TROWS][TSTRIDE];
    __shared__ float2 swt2[25];        // flipped weights, duplicated {w,w}
    const float NEG = -CUDART_INF_F;

    int bx   = blockIdx.x;
    int img  = bx / 7;              // b*C + c, 0..255  (magic-mul)
    int band = bx - img * 7;        // 0..6, 7 bands x 32 rows = 224
    int tid  = threadIdx.x;
    int u    = tid % 56;            // col-quad: owns cols 4u..4u+3
    int g    = tid / 56;            // row-group 0..3
    int y0   = band * RB;

    const float* xi = x + (size_t)img * (IH * IW);
    float* oi = out + (size_t)img * (IH * IW);
    const float* kc = kw + (img & (CCH - 1)) * 25;

    // swt2[i*5+j] = dup(kernel[c,0,4-i,4-j]) = dup(kc[24 - (5i+j)])
    if (tid < 25) {
        float w = __ldg(kc + (24 - tid));
        swt2[tid] = make_float2(w, w);
    }

    // ---- x-halo cols (always outside image): 36 rows x 4 cols -> -inf ----
    if (tid < 144) {
        int r = tid >> 2;
        int c = tid & 3;
        c = (c < 2) ? c : (c + 224);   // cols 0,1,226,227
        tile[r][c] = NEG;
    }

    // ---- stage bulk: 36 rows x 56 quads; thread (g,u) does rows g,g+4,...,g+32 ----
#pragma unroll
    for (int k = 0; k < 9; ++k) {
        int r = g + 4 * k;
        int gr = y0 - 2 + r;
        float4 v;
        if ((unsigned)gr < (unsigned)IH) {
            v = *(const float4*)(xi + gr * IW + 4 * u);
        } else {
            v.x = NEG; v.y = NEG; v.z = NEG; v.w = NEG;
        }
        float2* d = (float2*)&tile[r][4 * u + 2];   // 8B-aligned
        d[0] = make_float2(v.x, v.y);
        d[1] = make_float2(v.z, v.w);
    }
    __syncthreads();

    // ---- compute: thread (g,u) owns output rows y0+8g .. y0+8g+7, cols 4u..4u+3
    //      as 4 row-pairs; each pair shares a 6-row window (12 LDS.128).
    //      Per tap: 2 packed f32x2 adds + 4 scalar FMNMX. ----
    int x0 = 4 * u;
    int rbase = 8 * g;
    float* op = oi + (size_t)(y0 + rbase) * IW + x0;
    const u64* wt2 = (const u64*)swt2;

#pragma unroll
    for (int sp = 0; sp < 4; ++sp) {
        float a0 = NEG, a1 = NEG, a2 = NEG, a3 = NEG;   // output row rbase+2sp
        float b0 = NEG, b1 = NEG, b2 = NEG, b3 = NEG;   // output row rbase+2sp+1
        u64 wr2[5], wp2[5];
#pragma unroll
        for (int r = 0; r < 6; ++r) {
            const float* trow = &tile[rbase + 2 * sp + r][x0];
            float4 L = *(const float4*)(trow);      // global cols x0-2..x0+1
            float4 H = *(const float4*)(trow + 4);  // global cols x0+2..x0+5
            // window pairs P[j] = {W[j], W[j+1]}, j=0..6 (W[0..7] = L,H)
            u64 P[7];
            P[0] = pk(L.x, L.y);  P[1] = pk(L.y, L.z);
            P[2] = pk(L.z, L.w);  P[3] = pk(L.w, H.x);
            P[4] = pk(H.x, H.y);  P[5] = pk(H.y, H.z);
            P[6] = pk(H.z, H.w);
            if (r >= 1) {       // b-row reuses previous a-row weights (SSA rename)
#pragma unroll
                for (int j = 0; j < 5; ++j) wp2[j] = wr2[j];
            }
            if (r < 5) {        // a-accumulator: weight row r
#pragma unroll
                for (int j = 0; j < 5; ++j) {
                    u64 w2 = wt2[r * 5 + j];        // LDS.64 broadcast
                    wr2[j] = w2;
                    float s0, s1, t0, t1;
                    upk(s0, s1, fadd2(P[j], w2));
                    upk(t0, t1, fadd2(P[j + 2], w2));
                    a0 = fmaxf(a0, s0); a1 = fmaxf(a1, s1);
                    a2 = fmaxf(a2, t0); a3 = fmaxf(a3, t1);
                }
            }
            if (r >= 1) {       // b-accumulator: weight row r-1
#pragma unroll
                for (int j = 0; j < 5; ++j) {
                    u64 w2 = wp2[j];
                    float s0, s1, t0, t1;
                    upk(s0, s1, fadd2(P[j], w2));
                    upk(t0, t1, fadd2(P[j + 2], w2));
                    b0 = fmaxf(b0, s0); b1 = fmaxf(b1, s1);
                    b2 = fmaxf(b2, t0); b3 = fmaxf(b3, t1);
                }
            }
        }
        *(float4*)op = make_float4(a0, a1, a2, a3);
        op += IW;
        *(float4*)op = make_float4(b0, b1, b2, b3);
        op += IW;
    }
}

extern "C" void kernel_launch(void* const* d_in, const int* in_sizes, int n_in,
                              void* d_out, int out_size) {
    const float* x = (const float*)d_in[0];   // (8,32,224,224) fp32
    const float* k = (const float*)d_in[1];   // (32,1,5,5) fp32
    float* out = (float*)d_out;               // (8,32,224,224) fp32
    // 256 images x 7 y-bands = 1792 blocks; 224 thr = 4 row-groups x 56 col-quads
    tropical_conv2d_kernel<<<1792, 224>>>(x, k, out);
}

// round 15
// speedup vs baseline: 1.2674x; 1.2674x over previous
#include <cuda_runtime.h>
#include <math_constants.h>

#define IW 224
#define IH 224
#define CCH 32
#define RB 32          // output rows per block
#define TROWS 36       // RB + 4 halo
#define TSTRIDE 232    // 228 cols (224 + 4 halo) padded

// One window row: acc[0..3] (4 adjacent output cols) vs 8-wide window (L,H), weights w0..w4.
// Pure SSA — no local arrays, no MOVs.
__device__ __forceinline__ void acc_row(float& a0, float& a1, float& a2, float& a3,
                                        float4 L, float4 H,
                                        float w0, float w1, float w2, float w3, float w4) {
    a0 = fmaxf(a0, L.x + w0); a0 = fmaxf(a0, L.y + w1); a0 = fmaxf(a0, L.z + w2);
    a0 = fmaxf(a0, L.w + w3); a0 = fmaxf(a0, H.x + w4);
    a1 = fmaxf(a1, L.y + w0); a1 = fmaxf(a1, L.z + w1); a1 = fmaxf(a1, L.w + w2);
    a1 = fmaxf(a1, H.x + w3); a1 = fmaxf(a1, H.y + w4);
    a2 = fmaxf(a2, L.z + w0); a2 = fmaxf(a2, L.w + w1); a2 = fmaxf(a2, H.x + w2);
    a2 = fmaxf(a2, H.y + w3); a2 = fmaxf(a2, H.z + w4);
    a3 = fmaxf(a3, L.w + w0); a3 = fmaxf(a3, H.x + w1); a3 = fmaxf(a3, H.y + w2);
    a3 = fmaxf(a3, H.z + w3); a3 = fmaxf(a3, H.w + w4);
}

// out[b,c,y,x] = max_{i,j} x[b,c,y+i-2,x+j-2] + kernel[c,0,4-i,4-j], oob -> -inf
// tile[r][c]: global row y0-2+r, global col c-2. Cols 0,1,226,227 always -inf.
__global__ void __launch_bounds__(224, 5)
tropical_conv2d_kernel(const float* __restrict__ x,
                       const float* __restrict__ kw,
                       float* __restrict__ out) {
    __shared__ float tile[TROWS][TSTRIDE];
    __shared__ __align__(16) float swt[5][8];   // flipped weights, 32B-padded rows
    const float NEG = -CUDART_INF_F;

    int bx   = blockIdx.x;
    int img  = bx / 7;              // b*C + c, 0..255  (magic-mul)
    int band = bx - img * 7;        // 0..6, 7 bands x 32 rows = 224
    int tid  = threadIdx.x;
    int u    = tid % 56;            // col-quad: owns cols 4u..4u+3
    int g    = tid / 56;            // row-group 0..3
    int y0   = band * RB;

    const float* xi = x + (size_t)img * (IH * IW);
    float* oi = out + (size_t)img * (IH * IW);
    const float* kc = kw + (img & (CCH - 1)) * 25;

    // swt[i][j] = kernel[c,0,4-i,4-j] = kc[24 - (5i+j)]
    if (tid < 25) {
        int i = tid / 5, j = tid - 5 * i;
        swt[i][j] = __ldg(kc + (24 - tid));
    }

    // ---- x-halo cols (always outside image): 36 rows x 4 cols -> -inf ----
    if (tid < 144) {
        int r = tid >> 2;
        int c = tid & 3;
        c = (c < 2) ? c : (c + 224);   // cols 0,1,226,227
        tile[r][c] = NEG;
    }

    // ---- stage bulk: 36 rows x 56 quads; thread (g,u) does rows g,g+4,...,g+32 ----
    {
        const float* p = xi + (y0 - 2 + g) * IW + 4 * u;
        float* ts = &tile[g][4 * u + 2];
        if (band >= 1 && band <= 5) {
            // interior: all 36 tile rows in-image, no predicates
#pragma unroll
            for (int k = 0; k < 9; ++k) {
                float4 v = *(const float4*)p;
                ((float2*)ts)[0] = make_float2(v.x, v.y);   // 8B-aligned dest
                ((float2*)ts)[1] = make_float2(v.z, v.w);
                p += 4 * IW;
                ts += 4 * TSTRIDE;
            }
        } else {
#pragma unroll
            for (int k = 0; k < 9; ++k) {
                int gr = y0 - 2 + g + 4 * k;
                float4 v;
                if ((unsigned)gr < (unsigned)IH) {
                    v = *(const float4*)p;
                } else {
                    v.x = NEG; v.y = NEG; v.z = NEG; v.w = NEG;
                }
                ((float2*)ts)[0] = make_float2(v.x, v.y);
                ((float2*)ts)[1] = make_float2(v.z, v.w);
                p += 4 * IW;
                ts += 4 * TSTRIDE;
            }
        }
    }
    __syncthreads();

    // ---- compute: thread (g,u) owns output rows y0+8g .. y0+8g+7, cols 4u..4u+3
    //      as 4 row-pairs; each pair shares a 6-row window (12 LDS.128).
    //      Weight row r JIT from smem (LDS.128 + LDS.32); b-path reuses last row's regs. ----
    int x0 = 4 * u;
    int rbase = 8 * g;
    float* op = oi + (size_t)(y0 + rbase) * IW + x0;

#pragma unroll
    for (int sp = 0; sp < 4; ++sp) {
        float a0 = NEG, a1 = NEG, a2 = NEG, a3 = NEG;   // output row rbase+2sp
        float b0 = NEG, b1 = NEG, b2 = NEG, b3 = NEG;   // output row rbase+2sp+1
        float wr0, wr1, wr2, wr3, wr4;                  // weight row r (a-path)
        float wp0, wp1, wp2, wp3, wp4;                  // weight row r-1 (b-path)
        wr0 = wr1 = wr2 = wr3 = wr4 = NEG;              // dead before first use
#pragma unroll
        for (int r = 0; r < 6; ++r) {
            const float* trow = &tile[rbase + 2 * sp + r][x0];
            float4 L = *(const float4*)(trow);      // global cols x0-2..x0+1
            float4 H = *(const float4*)(trow + 4);  // global cols x0+2..x0+5
            if (r >= 1) {       // b-row uses previous a-row weights (SSA rename)
                wp0 = wr0; wp1 = wr1; wp2 = wr2; wp3 = wr3; wp4 = wr4;
            }
            if (r < 5) {        // load weight row r: one LDS.128 + one LDS.32 (broadcast)
                float4 wv = *(const float4*)&swt[r][0];
                float we = swt[r][4];
                wr0 = wv.x; wr1 = wv.y; wr2 = wv.z; wr3 = wv.w; wr4 = we;
                acc_row(a0, a1, a2, a3, L, H, wr0, wr1, wr2, wr3, wr4);
            }
            if (r >= 1) {
                acc_row(b0, b1, b2, b3, L, H, wp0, wp1, wp2, wp3, wp4);
            }
        }
        *(float4*)op = make_float4(a0, a1, a2, a3);
        op += IW;
        *(float4*)op = make_float4(b0, b1, b2, b3);
        op += IW;
    }
}

extern "C" void kernel_launch(void* const* d_in, const int* in_sizes, int n_in,
                              void* d_out, int out_size) {
    const float* x = (const float*)d_in[0];   // (8,32,224,224) fp32
    const float* k = (const float*)d_in[1];   // (32,1,5,5) fp32
    float* out = (float*)d_out;               // (8,32,224,224) fp32
    // 256 images x 7 y-bands = 1792 blocks; 224 thr = 4 row-groups x 56 col-quads
    tropical_conv2d_kernel<<<1792, 224>>>(x, k, out);
}